// round 1
// baseline (speedup 1.0000x reference)
#include <cuda_runtime.h>
#include <math.h>

// Problem constants
#define RR 2048           // bs*NA
#define NEN 16
#define NALLY 15
#define REN (RR*NEN)      // 32768 enemy rows
#define RAL (RR*NALLY)    // 30720 ally rows
#define HH 64
#define HDD 4
#define OD 256            // HH*HDD
#define FD 10             // END == ALD == 10
#define KK 650            // 64*10 + 10 (bias lanes)

// Scratch (static device globals -- no allocation allowed)
__device__ float g_He[REN*HH];
__device__ float g_Ha[RAL*HH];
__device__ float g_EmbEn[RR*OD];
__device__ float g_EmbAl4[RAL*OD];
__device__ float g_EmbAlSum[RR*OD];
__device__ float g_PassEmb[RR*3];

__device__ __forceinline__ void atomicMaxFloat(float* addr, float value) {
    int* ia = (int*)addr;
    int old = *ia;
    while (__int_as_float(old) < value) {
        int assumed = old;
        old = atomicCAS(ia, assumed, __float_as_int(value));
        if (old == assumed) break;
    }
}

__global__ void init_pass_kernel() {
    int i = blockIdx.x * blockDim.x + threadIdx.x;
    if (i < RR*3) g_PassEmb[i] = -INFINITY;
}

// hidden = relu(feats @ w1 + b1) : feats [nrows,10], w1 [10,64]
__global__ void hidden_kernel(const float* __restrict__ feats,
                              const float* __restrict__ w1,
                              const float* __restrict__ b1,
                              int nrows, int is_ally) {
    int idx = blockIdx.x * blockDim.x + threadIdx.x;
    if (idx >= nrows * HH) return;
    int row = idx >> 6, j = idx & 63;
    const float* f = feats + row * FD;
    float s = b1[j];
#pragma unroll
    for (int i = 0; i < FD; i++) s = fmaf(f[i], w1[i*HH + j], s);
    s = fmaxf(s, 0.f);
    (is_ally ? g_Ha : g_He)[idx] = s;
}

// Bilinear GEMM: for each row r (enemy or ally), with h = hidden[r] (64), e = feats[r] (10):
//   out[r, o] = sum_{k,i} h[k]*e[i]*W2[k*strideK + i*256 + o] + sum_i e[i]*b2[i*256 + o]
// Block handles NR consecutive rows (all belonging to one agent). o = threadIdx.x in [0,256).
template<int NR, bool ENEMY>
__global__ void __launch_bounds__(256) bilinear_kernel(const float* __restrict__ feats,
                                                       const float* __restrict__ W2,
                                                       const float* __restrict__ b2,
                                                       int strideK) {
    __shared__ float a_sh[KK * 16];   // [kk][rr], rr stride 16 (padded), 41.6 KB
    const int o = threadIdx.x;
    const int r0 = blockIdx.x;
    const int rowbase = r0 * NR;
    const float* __restrict__ Hs = ENEMY ? g_He : g_Ha;

    // Build A tile: a[kk<640] = h[kk/10]*e[kk%10]; a[640+i] = e[i]
    for (int idx = o; idx < KK * 16; idx += 256) {
        int kk = idx >> 4, rr = idx & 15;
        float v = 0.f;
        if (rr < NR) {
            int row = rowbase + rr;
            if (kk < 640) {
                int k = kk / 10, i = kk - k * 10;
                v = Hs[row*HH + k] * feats[row*FD + i];
            } else {
                v = feats[row*FD + (kk - 640)];
            }
        }
        a_sh[idx] = v;
    }
    __syncthreads();

    float acc[16];
#pragma unroll
    for (int q = 0; q < 16; q++) acc[q] = 0.f;

    for (int k = 0; k < 64; k++) {
        const float* w = W2 + k * strideK + o;
#pragma unroll
        for (int i = 0; i < 10; i++) {
            float wv = __ldg(w + i * OD);
            const float4* ar = (const float4*)(a_sh + (k*10 + i) * 16);
#pragma unroll
            for (int q = 0; q < 4; q++) {
                float4 a4 = ar[q];
                acc[q*4+0] = fmaf(a4.x, wv, acc[q*4+0]);
                acc[q*4+1] = fmaf(a4.y, wv, acc[q*4+1]);
                acc[q*4+2] = fmaf(a4.z, wv, acc[q*4+2]);
                acc[q*4+3] = fmaf(a4.w, wv, acc[q*4+3]);
            }
        }
    }
    // bias lanes
#pragma unroll
    for (int i = 0; i < 10; i++) {
        float wv = __ldg(b2 + i * OD + o);
        const float4* ar = (const float4*)(a_sh + (640 + i) * 16);
#pragma unroll
        for (int q = 0; q < 4; q++) {
            float4 a4 = ar[q];
            acc[q*4+0] = fmaf(a4.x, wv, acc[q*4+0]);
            acc[q*4+1] = fmaf(a4.y, wv, acc[q*4+1]);
            acc[q*4+2] = fmaf(a4.z, wv, acc[q*4+2]);
            acc[q*4+3] = fmaf(a4.w, wv, acc[q*4+3]);
        }
    }

    if (ENEMY) {
        float sum = 0.f;
#pragma unroll
        for (int q = 0; q < 16; q++) sum += acc[q];
        g_EmbEn[r0*OD + o] = sum;
    } else {
        float sum = 0.f;
#pragma unroll
        for (int q = 0; q < NR; q++) {
            g_EmbAl4[(rowbase + q)*OD + o] = acc[q];
            sum += acc[q];
        }
        g_EmbAlSum[r0*OD + o] = sum;
    }
}

// Passing MLP per ally row: p = relu(emb_al4 @ pw1 + pb1) @ pw2 + pb2 ; mean over heads; atomicMax over allies
__global__ void __launch_bounds__(256) passing_kernel(const float* __restrict__ pw1,
                                                      const float* __restrict__ pb1,
                                                      const float* __restrict__ pw2,
                                                      const float* __restrict__ pb2) {
    __shared__ float emb_sh[OD];
    __shared__ float t_sh[OD];
    __shared__ float p_sh[12];
    const int arow = blockIdx.x;        // ally row 0..RAL-1
    const int r = arow / NALLY;
    const int tid = threadIdx.x;        // 256
    emb_sh[tid] = g_EmbAl4[arow*OD + tid];
    __syncthreads();
    int hd = tid >> 6, j = tid & 63;
    float s = pb1[j];
#pragma unroll
    for (int k = 0; k < 64; k++) s = fmaf(emb_sh[hd*64 + k], pw1[k*64 + j], s);
    t_sh[tid] = fmaxf(s, 0.f);
    __syncthreads();
    if (tid < 12) {
        int h2 = tid / 3, c = tid - h2*3;
        float s2 = 0.f;
        for (int m = 0; m < 64; m++) s2 = fmaf(t_sh[h2*64 + m], pw2[m*3 + c], s2);
        p_sh[tid] = s2;
    }
    __syncthreads();
    if (tid < 3) {
        float v = 0.25f*(p_sh[tid] + p_sh[3+tid] + p_sh[6+tid] + p_sh[9+tid]) + pb2[tid];
        atomicMaxFloat(&g_PassEmb[r*3 + tid], v);
    }
}

// Final: own-embed + merger softmax + GRU + fc2 + concat outputs
__global__ void __launch_bounds__(64) final_kernel(
    const float* __restrict__ own,
    const float* __restrict__ fc1_w, const float* __restrict__ fc1_b,
    const float* __restrict__ merger_w,
    const float* __restrict__ hstate,
    const float* __restrict__ wih, const float* __restrict__ whh,
    const float* __restrict__ bih, const float* __restrict__ bhh,
    const float* __restrict__ fc2_w1, const float* __restrict__ fc2_b1,
    const float* __restrict__ fc2_w2, const float* __restrict__ fc2_b2,
    float* __restrict__ out_q, float* __restrict__ out_h) {
    __shared__ float own_sh[32];
    __shared__ float x_sh[64];
    __shared__ float h_sh[64];
    __shared__ float hh_sh[64];
    __shared__ float t_sh[64];
    const int r = blockIdx.x;
    const int j = threadIdx.x;   // 64 threads
    if (j < 30) own_sh[j] = own[r*30 + j];
    h_sh[j] = hstate[r*64 + j];
    __syncthreads();

    float eo = fc1_b[j];
#pragma unroll
    for (int i = 0; i < 30; i++) eo = fmaf(own_sh[i], fc1_w[i*64 + j], eo);

    // softmax over HD of merger_w[:, j]
    float w0 = merger_w[j], w1v = merger_w[64+j], w2v = merger_w[128+j], w3v = merger_w[192+j];
    float mx = fmaxf(fmaxf(w0, w1v), fmaxf(w2v, w3v));
    float e0 = expf(w0-mx), e1 = expf(w1v-mx), e2 = expf(w2v-mx), e3 = expf(w3v-mx);
    float inv = 1.f / (e0+e1+e2+e3);
    const float* en = g_EmbEn + r*OD;
    const float* al = g_EmbAlSum + r*OD;
    float m = e0*inv*(en[j]      + al[j])
            + e1*inv*(en[64+j]   + al[64+j])
            + e2*inv*(en[128+j]  + al[128+j])
            + e3*inv*(en[192+j]  + al[192+j]);

    float x = fmaxf(eo + m, 0.f);
    x_sh[j] = x;
    __syncthreads();

    float gi[3], gh[3];
#pragma unroll
    for (int t = 0; t < 3; t++) {
        int g = t*64 + j;
        float si = bih[g], sh = bhh[g];
        const float* wi = wih + g*64;
        const float* wh = whh + g*64;
#pragma unroll 8
        for (int k = 0; k < 64; k++) {
            si = fmaf(x_sh[k], __ldg(wi + k), si);
            sh = fmaf(h_sh[k], __ldg(wh + k), sh);
        }
        gi[t] = si; gh[t] = sh;
    }
    float rg = 1.f/(1.f + expf(-(gi[0]+gh[0])));
    float zg = 1.f/(1.f + expf(-(gi[1]+gh[1])));
    float ng = tanhf(gi[2] + rg*gh[2]);
    float hh = (1.f - zg)*ng + zg*h_sh[j];
    hh_sh[j] = hh;
    out_h[r*64 + j] = hh;
    __syncthreads();

    float tt = fc2_b1[j];
#pragma unroll 8
    for (int k = 0; k < 64; k++) tt = fmaf(hh_sh[k], fc2_w1[k*64 + j], tt);
    t_sh[j] = fmaxf(tt, 0.f);
    __syncthreads();

    if (j < 19) {
        float q = fc2_b2[j];
        for (int mm = 0; mm < 64; mm++) q = fmaf(t_sh[mm], fc2_w2[mm*19 + j], q);
        int col = (j < 9) ? j : j + 3;
        out_q[r*22 + col] = q;
    }
    if (j < 3) out_q[r*22 + 9 + j] = g_PassEmb[r*3 + j];
}

extern "C" void kernel_launch(void* const* d_in, const int* in_sizes, int n_in,
                              void* d_out, int out_size) {
    const float* own    = (const float*)d_in[1];
    const float* ally   = (const float*)d_in[2];
    const float* enemy  = (const float*)d_in[3];
    const float* hstate = (const float*)d_in[4];
    const float* fc1_w  = (const float*)d_in[5];
    const float* fc1_b  = (const float*)d_in[6];
    const float* he_w1  = (const float*)d_in[7];
    const float* he_b1  = (const float*)d_in[8];
    const float* he_w2  = (const float*)d_in[9];
    const float* he_b2  = (const float*)d_in[10];
    const float* ha_w1  = (const float*)d_in[11];
    const float* ha_b1  = (const float*)d_in[12];
    const float* ha_w2  = (const float*)d_in[13];
    const float* ha_b2  = (const float*)d_in[14];
    const float* merger = (const float*)d_in[15];
    const float* wih    = (const float*)d_in[16];
    const float* whh    = (const float*)d_in[17];
    const float* bih    = (const float*)d_in[18];
    const float* bhh    = (const float*)d_in[19];
    const float* fc2_w1 = (const float*)d_in[20];
    const float* fc2_b1 = (const float*)d_in[21];
    const float* fc2_w2 = (const float*)d_in[22];
    const float* fc2_b2 = (const float*)d_in[23];
    const float* pw1    = (const float*)d_in[24];
    const float* pb1    = (const float*)d_in[25];
    const float* pw2    = (const float*)d_in[26];
    const float* pb2    = (const float*)d_in[27];

    float* out   = (float*)d_out;
    float* out_q = out;              // [2048, 22]
    float* out_h = out + RR*22;      // [2048, 64]

    init_pass_kernel<<<(RR*3 + 255)/256, 256>>>();
    hidden_kernel<<<(REN*HH)/256, 256>>>(enemy, he_w1, he_b1, REN, 0);
    hidden_kernel<<<(RAL*HH)/256, 256>>>(ally,  ha_w1, ha_b1, RAL, 1);
    bilinear_kernel<16, true ><<<RR, 256>>>(enemy, he_w2, he_b2, 2820);
    bilinear_kernel<15, false><<<RR, 256>>>(ally,  ha_w2, ha_b2, 2560);
    passing_kernel<<<RAL, 256>>>(pw1, pb1, pw2, pb2);
    final_kernel<<<RR, 64>>>(own, fc1_w, fc1_b, merger, hstate,
                             wih, whh, bih, bhh,
                             fc2_w1, fc2_b1, fc2_w2, fc2_b2,
                             out_q, out_h);
}

// round 3
// speedup vs baseline: 1.5636x; 1.5636x over previous
#include <cuda_runtime.h>
#include <math.h>

// Problem constants
#define RR 2048           // bs*NA
#define NEN 16
#define NALLY 15
#define HH 64
#define HDD 4
#define OD 256            // HH*HDD
#define FD 10             // END == ALD == 10
#define KK 650            // 64*10 + 10 bias lanes

// Scratch (static device globals -- no allocation allowed)
__device__ float g_EmbEn[RR*OD];
__device__ float g_EmbAlSum[RR*OD];
__device__ float g_PassEmb[RR*3];

typedef unsigned long long ull;

__device__ __forceinline__ ull ffma2(ull a, ull b, ull c) {
    ull d;
    asm("fma.rn.f32x2 %0, %1, %2, %3;" : "=l"(d) : "l"(a), "l"(b), "l"(c));
    return d;
}
__device__ __forceinline__ ull pack2(float x, float y) {
    ull d;
    asm("mov.b64 %0, {%1, %2};" : "=l"(d) : "f"(x), "f"(y));
    return d;
}
__device__ __forceinline__ float2 unpack2(ull v) {
    float2 r;
    asm("mov.b64 {%0, %1}, %2;" : "=f"(r.x), "=f"(r.y) : "l"(v));
    return r;
}

// Fused: hidden MLP + bilinear hypernet GEMM (+ passing MLP epilogue for allies).
// One block per agent. 128 threads; thread owns output columns c0=2*tid, c0+1.
// Rows: NR entities (16 enemies / 15 allies), padded to 16 with zeros.
//   out[r,o] = sum_{k,i} h[k,r]*e[i,r]*W2[k*strideK + i*256 + o] + sum_i e[i,r]*b2[i*256+o]
template<int NR, bool ENEMY>
__global__ void __launch_bounds__(128) bilinear2_kernel(
    const float* __restrict__ feats,
    const float* __restrict__ W1, const float* __restrict__ B1,
    const float* __restrict__ W2, const float* __restrict__ B2, int strideK,
    const float* __restrict__ pw1, const float* __restrict__ pb1,
    const float* __restrict__ pw2, const float* __restrict__ pb2)
{
    __shared__ __align__(16) float a_sh[KK*16];   // 41.6 KB, reused by epilogue
    __shared__ __align__(16) float h_sh[HH*16];   // h transposed: [k*16 + rr]
    __shared__ __align__(16) float e_sh[16*FD];

    const int tid = threadIdx.x;
    const int r0 = blockIdx.x;
    const int rowbase = r0 * NR;

    // ---- load entity feats e (zero-pad rows >= NR) ----
    // NOTE: 160 entries, 128 threads -> strided loop (R2 bug: single guarded store
    // left e_sh[128..159] uninitialized).
    for (int idx = tid; idx < 16*FD; idx += 128) {
        float v = 0.f;
        if (idx < NR*FD) v = feats[rowbase*FD + idx];
        e_sh[idx] = v;
    }
    __syncthreads();

    // ---- h = relu(e @ W1 + B1), transposed layout [k][rr], zero for padded rows ----
#pragma unroll
    for (int p = 0; p < 8; p++) {
        int idx = tid + p*128;
        int rr = idx & 15, k = idx >> 4;
        float s = 0.f;
        if (rr < NR) {
            s = B1[k];
#pragma unroll
            for (int i = 0; i < FD; i++) s = fmaf(e_sh[rr*FD + i], __ldg(W1 + i*HH + k), s);
            s = fmaxf(s, 0.f);
        }
        h_sh[idx] = s;   // h_sh[k*16 + rr]
    }
    __syncthreads();

    // ---- build A tile: a_sh[kk*16 + rr] ----
    for (int idx = tid; idx < KK*16; idx += 128) {
        int kk = idx >> 4, rr = idx & 15;
        float v;
        if (kk < 640) {
            int k = kk / 10, i = kk - k*10;
            v = h_sh[k*16 + rr] * e_sh[rr*FD + i];
        } else {
            v = e_sh[rr*FD + (kk - 640)];   // bias lane (e, zero-padded)
        }
        a_sh[idx] = v;
    }
    __syncthreads();

    // ---- main loop: packed f32x2, rows in pairs, 2 output columns per thread ----
    const int c0 = tid * 2;
    ull acc[8][2];
#pragma unroll
    for (int p = 0; p < 8; p++) { acc[p][0] = 0ull; acc[p][1] = 0ull; }

    for (int k = 0; k < 64; k++) {
        const float* wk = W2 + k*strideK + c0;
#pragma unroll
        for (int i = 0; i < 10; i++) {
            float2 wv = __ldg((const float2*)(wk + i*OD));
            ull w0 = pack2(wv.x, wv.x);
            ull w1d = pack2(wv.y, wv.y);
            const ulonglong2* ar = (const ulonglong2*)(a_sh + (k*10 + i)*16);
#pragma unroll
            for (int q = 0; q < 4; q++) {
                ulonglong2 av = ar[q];
                acc[2*q  ][0] = ffma2(av.x, w0,  acc[2*q  ][0]);
                acc[2*q  ][1] = ffma2(av.x, w1d, acc[2*q  ][1]);
                acc[2*q+1][0] = ffma2(av.y, w0,  acc[2*q+1][0]);
                acc[2*q+1][1] = ffma2(av.y, w1d, acc[2*q+1][1]);
            }
        }
    }
    // bias lanes (A rows 640..649 hold e)
#pragma unroll
    for (int i = 0; i < 10; i++) {
        float2 wv = __ldg((const float2*)(B2 + i*OD + c0));
        ull w0 = pack2(wv.x, wv.x);
        ull w1d = pack2(wv.y, wv.y);
        const ulonglong2* ar = (const ulonglong2*)(a_sh + (640 + i)*16);
#pragma unroll
        for (int q = 0; q < 4; q++) {
            ulonglong2 av = ar[q];
            acc[2*q  ][0] = ffma2(av.x, w0,  acc[2*q  ][0]);
            acc[2*q  ][1] = ffma2(av.x, w1d, acc[2*q  ][1]);
            acc[2*q+1][0] = ffma2(av.y, w0,  acc[2*q+1][0]);
            acc[2*q+1][1] = ffma2(av.y, w1d, acc[2*q+1][1]);
        }
    }

    // ---- row-sum (sum over entities) ----
    float s0 = 0.f, s1 = 0.f;
#pragma unroll
    for (int p = 0; p < 8; p++) {
        float2 f0 = unpack2(acc[p][0]);
        float2 f1 = unpack2(acc[p][1]);
        s0 += f0.x + f0.y;
        s1 += f1.x + f1.y;
    }

    if (ENEMY) {
        g_EmbEn[r0*OD + c0]     = s0;
        g_EmbEn[r0*OD + c0 + 1] = s1;
        return;
    }

    g_EmbAlSum[r0*OD + c0]     = s0;
    g_EmbAlSum[r0*OD + c0 + 1] = s1;

    // ======== ally-only: fused passing MLP over the 15 allies of this agent ========
    // stage emb transposed into a_sh: emb[c][row], stride 20 floats (16B-aligned, de-conflicted)
    __syncthreads();   // all threads done reading a_sh
    float* emb_sh = a_sh;            // 256*20 = 5120 floats
    float* t_sh   = a_sh + 5120;     // 256*20 = 5120 floats (total 10240 <= 10400)
#pragma unroll
    for (int p = 0; p < 8; p++) {
        *(ull*)(emb_sh + c0*20 + 2*p)       = acc[p][0];   // rows 2p, 2p+1 of col c0
        *(ull*)(emb_sh + (c0+1)*20 + 2*p)   = acc[p][1];
    }
    __syncthreads();

    // layer 1: t[row][hd*64+j] = relu(pb1[j] + sum_k emb[row][hd*64+k]*pw1[k*64+j])
    // thread covers (hd,j) = tid and tid+128; all 16 rows packed in f32x2 pairs
#pragma unroll
    for (int s = 0; s < 2; s++) {
        int hdj = tid + 128*s;
        int hd = hdj >> 6, j = hdj & 63;
        ull at[8];
#pragma unroll
        for (int p = 0; p < 8; p++) at[p] = 0ull;
        for (int k = 0; k < 64; k++) {
            float wv = __ldg(pw1 + k*HH + j);
            ull wd = pack2(wv, wv);
            const ulonglong2* er = (const ulonglong2*)(emb_sh + (hd*64 + k)*20);
#pragma unroll
            for (int q = 0; q < 4; q++) {
                ulonglong2 ev = er[q];
                at[2*q]   = ffma2(ev.x, wd, at[2*q]);
                at[2*q+1] = ffma2(ev.y, wd, at[2*q+1]);
            }
        }
        float bb = pb1[j];
#pragma unroll
        for (int p = 0; p < 8; p++) {
            float2 f = unpack2(at[p]);
            f.x = fmaxf(f.x + bb, 0.f);
            f.y = fmaxf(f.y + bb, 0.f);
            *(ull*)(t_sh + hdj*20 + 2*p) = pack2(f.x, f.y);
        }
    }
    __syncthreads();

    // layer 2: p[row][hd][c] = sum_m t[row][hd*64+m]*pw2[m*3+c]; 12 threads (hd,c)
    if (tid < 12) {
        int hd = tid / 3, c = tid - hd*3;
        ull ap[8];
#pragma unroll
        for (int p = 0; p < 8; p++) ap[p] = 0ull;
        for (int m = 0; m < 64; m++) {
            float wv = __ldg(pw2 + m*3 + c);
            ull wd = pack2(wv, wv);
            const ulonglong2* tr = (const ulonglong2*)(t_sh + (hd*64 + m)*20);
#pragma unroll
            for (int q = 0; q < 4; q++) {
                ulonglong2 tv = tr[q];
                ap[2*q]   = ffma2(tv.x, wd, ap[2*q]);
                ap[2*q+1] = ffma2(tv.y, wd, ap[2*q+1]);
            }
        }
        // store p[hd][c][row] into h_sh (reused): h_sh[(hd*3+c)*16 + row]
#pragma unroll
        for (int p = 0; p < 8; p++) {
            float2 f = unpack2(ap[p]);
            h_sh[tid*16 + 2*p]     = f.x;
            h_sh[tid*16 + 2*p + 1] = f.y;
        }
    }
    __syncthreads();

    // mean over heads, max over allies (rows 0..14 only; row 15 is padding)
    if (tid < 3) {
        float mx = -INFINITY;
        float bb = pb2[tid];
        for (int row = 0; row < NALLY; row++) {
            float v = 0.25f * (h_sh[(0*3 + tid)*16 + row] + h_sh[(1*3 + tid)*16 + row] +
                               h_sh[(2*3 + tid)*16 + row] + h_sh[(3*3 + tid)*16 + row]) + bb;
            mx = fmaxf(mx, v);
        }
        g_PassEmb[r0*3 + tid] = mx;
    }
}

// Final: own-embed + merger softmax + GRU + fc2 + concat outputs
__global__ void __launch_bounds__(64) final_kernel(
    const float* __restrict__ own,
    const float* __restrict__ fc1_w, const float* __restrict__ fc1_b,
    const float* __restrict__ merger_w,
    const float* __restrict__ hstate,
    const float* __restrict__ wih, const float* __restrict__ whh,
    const float* __restrict__ bih, const float* __restrict__ bhh,
    const float* __restrict__ fc2_w1, const float* __restrict__ fc2_b1,
    const float* __restrict__ fc2_w2, const float* __restrict__ fc2_b2,
    float* __restrict__ out_q, float* __restrict__ out_h) {
    __shared__ float own_sh[32];
    __shared__ float x_sh[64];
    __shared__ float h_sh[64];
    __shared__ float hh_sh[64];
    __shared__ float t_sh[64];
    const int r = blockIdx.x;
    const int j = threadIdx.x;   // 64 threads
    if (j < 30) own_sh[j] = own[r*30 + j];
    h_sh[j] = hstate[r*64 + j];
    __syncthreads();

    float eo = fc1_b[j];
#pragma unroll
    for (int i = 0; i < 30; i++) eo = fmaf(own_sh[i], fc1_w[i*64 + j], eo);

    // softmax over HD of merger_w[:, j]
    float w0 = merger_w[j], w1v = merger_w[64+j], w2v = merger_w[128+j], w3v = merger_w[192+j];
    float mx = fmaxf(fmaxf(w0, w1v), fmaxf(w2v, w3v));
    float e0 = expf(w0-mx), e1 = expf(w1v-mx), e2 = expf(w2v-mx), e3 = expf(w3v-mx);
    float inv = 1.f / (e0+e1+e2+e3);
    const float* en = g_EmbEn + r*OD;
    const float* al = g_EmbAlSum + r*OD;
    float m = e0*inv*(en[j]      + al[j])
            + e1*inv*(en[64+j]   + al[64+j])
            + e2*inv*(en[128+j]  + al[128+j])
            + e3*inv*(en[192+j]  + al[192+j]);

    float x = fmaxf(eo + m, 0.f);
    x_sh[j] = x;
    __syncthreads();

    float gi[3], gh[3];
#pragma unroll
    for (int t = 0; t < 3; t++) {
        int g = t*64 + j;
        float si = bih[g], sh = bhh[g];
        const float* wi = wih + g*64;
        const float* wh = whh + g*64;
#pragma unroll 8
        for (int k = 0; k < 64; k++) {
            si = fmaf(x_sh[k], __ldg(wi + k), si);
            sh = fmaf(h_sh[k], __ldg(wh + k), sh);
        }
        gi[t] = si; gh[t] = sh;
    }
    float rg = 1.f/(1.f + expf(-(gi[0]+gh[0])));
    float zg = 1.f/(1.f + expf(-(gi[1]+gh[1])));
    float ng = tanhf(gi[2] + rg*gh[2]);
    float hh = (1.f - zg)*ng + zg*h_sh[j];
    hh_sh[j] = hh;
    out_h[r*64 + j] = hh;
    __syncthreads();

    float tt = fc2_b1[j];
#pragma unroll 8
    for (int k = 0; k < 64; k++) tt = fmaf(hh_sh[k], fc2_w1[k*64 + j], tt);
    t_sh[j] = fmaxf(tt, 0.f);
    __syncthreads();

    if (j < 19) {
        float q = fc2_b2[j];
        for (int mm = 0; mm < 64; mm++) q = fmaf(t_sh[mm], fc2_w2[mm*19 + j], q);
        int col = (j < 9) ? j : j + 3;
        out_q[r*22 + col] = q;
    }
    if (j < 3) out_q[r*22 + 9 + j] = g_PassEmb[r*3 + j];
}

extern "C" void kernel_launch(void* const* d_in, const int* in_sizes, int n_in,
                              void* d_out, int out_size) {
    const float* own    = (const float*)d_in[1];
    const float* ally   = (const float*)d_in[2];
    const float* enemy  = (const float*)d_in[3];
    const float* hstate = (const float*)d_in[4];
    const float* fc1_w  = (const float*)d_in[5];
    const float* fc1_b  = (const float*)d_in[6];
    const float* he_w1  = (const float*)d_in[7];
    const float* he_b1  = (const float*)d_in[8];
    const float* he_w2  = (const float*)d_in[9];
    const float* he_b2  = (const float*)d_in[10];
    const float* ha_w1  = (const float*)d_in[11];
    const float* ha_b1  = (const float*)d_in[12];
    const float* ha_w2  = (const float*)d_in[13];
    const float* ha_b2  = (const float*)d_in[14];
    const float* merger = (const float*)d_in[15];
    const float* wih    = (const float*)d_in[16];
    const float* whh    = (const float*)d_in[17];
    const float* bih    = (const float*)d_in[18];
    const float* bhh    = (const float*)d_in[19];
    const float* fc2_w1 = (const float*)d_in[20];
    const float* fc2_b1 = (const float*)d_in[21];
    const float* fc2_w2 = (const float*)d_in[22];
    const float* fc2_b2 = (const float*)d_in[23];
    const float* pw1    = (const float*)d_in[24];
    const float* pb1    = (const float*)d_in[25];
    const float* pw2    = (const float*)d_in[26];
    const float* pb2    = (const float*)d_in[27];

    float* out   = (float*)d_out;
    float* out_q = out;              // [2048, 22]
    float* out_h = out + RR*22;      // [2048, 64]

    bilinear2_kernel<16, true ><<<RR, 128>>>(enemy, he_w1, he_b1, he_w2, he_b2, 2820,
                                             pw1, pb1, pw2, pb2);
    bilinear2_kernel<15, false><<<RR, 128>>>(ally,  ha_w1, ha_b1, ha_w2, ha_b2, 2560,
                                             pw1, pb1, pw2, pb2);
    final_kernel<<<RR, 64>>>(own, fc1_w, fc1_b, merger, hstate,
                             wih, whh, bih, bhh,
                             fc2_w1, fc2_b1, fc2_w2, fc2_b2,
                             out_q, out_h);
}

// round 4
// speedup vs baseline: 2.1373x; 1.3669x over previous
#include <cuda_runtime.h>
#include <math.h>

// Problem constants
#define RR 2048           // bs*NA
#define NEN 16
#define NALLY 15
#define HH 64
#define HDD 4
#define OD 256            // HH*HDD
#define FD 10             // END == ALD == 10
#define KK 650            // 64*10 + 10 bias lanes

// Scratch (static device globals -- no allocation allowed)
__device__ float g_W2p[KK*OD];       // ally W2 folded with pw1 (650x256)
__device__ float g_EmbEn[RR*OD];
__device__ float g_EmbAlSum[RR*OD];
__device__ float g_PassEmb[RR*3];

typedef unsigned long long ull;

__device__ __forceinline__ ull ffma2(ull a, ull b, ull c) {
    ull d;
    asm("fma.rn.f32x2 %0, %1, %2, %3;" : "=l"(d) : "l"(a), "l"(b), "l"(c));
    return d;
}
__device__ __forceinline__ ull pack2(float x, float y) {
    ull d;
    asm("mov.b64 %0, {%1, %2};" : "=l"(d) : "f"(x), "f"(y));
    return d;
}
__device__ __forceinline__ float2 unpack2(ull v) {
    float2 r;
    asm("mov.b64 {%0, %1}, %2;" : "=f"(r.x), "=f"(r.y) : "l"(v));
    return r;
}

// ---------------------------------------------------------------------------
// W2p[kk, hd*64+j] = sum_h W2full_al[kk, hd*64+h] * pw1[h*64+j]
// W2full_al rows: kk<640 -> ha_w2[k*2560 + i*256 + m]; kk>=640 -> ha_b2[(kk-640)*256+m]
__global__ void __launch_bounds__(256) w2p_kernel(const float* __restrict__ ha_w2,
                                                  const float* __restrict__ ha_b2,
                                                  const float* __restrict__ pw1) {
    __shared__ float wrow[256];
    const int kk = blockIdx.x;
    const int o  = threadIdx.x;
    float v;
    if (kk < 640) { int k = kk/10, i = kk - k*10; v = ha_w2[k*2560 + i*256 + o]; }
    else          { v = ha_b2[(kk-640)*256 + o]; }
    wrow[o] = v;
    __syncthreads();
    const int hd = o >> 6, j = o & 63;
    float s = 0.f;
#pragma unroll
    for (int h = 0; h < 64; h++) s = fmaf(wrow[hd*64 + h], __ldg(pw1 + h*64 + j), s);
    g_W2p[kk*256 + o] = s;
}

// ---------------------------------------------------------------------------
// Summed bilinear: per agent, row-sum the A-rows FIRST, then one [650]x[650,256].
// 16 agents per block ("rows" of the tile = agents). Grid = RR/16 = 128.
template<int NR, bool ENEMY>
__global__ void __launch_bounds__(128) summed_kernel(
    const float* __restrict__ feats,
    const float* __restrict__ W1, const float* __restrict__ B1,
    const float* __restrict__ W2, const float* __restrict__ B2, int strideK)
{
    __shared__ __align__(16) float a_sh[KK*16];   // [kk][agent]
    __shared__ float e_sh[16*161];                // [agent][rr*10+i], stride 161 (bank-spread)
    const int tid = threadIdx.x;
    const int ag0 = blockIdx.x * 16;

    // stage e for 16 agents (contiguous in gmem)
    for (int idx = tid; idx < 16*NR*FD; idx += 128) {
        int a = idx / (NR*FD), rem = idx - a*(NR*FD);
        e_sh[a*161 + rem] = feats[(ag0*NR)*FD + idx];
    }
    __syncthreads();

    // build a_sh: thread owns 8 (k, agent) pairs
#pragma unroll
    for (int p = 0; p < 8; p++) {
        int idx = tid + p*128;
        int a = idx & 15, k = idx >> 4;
        const float* ea = e_sh + a*161;
        float h[NR];
#pragma unroll
        for (int rr = 0; rr < NR; rr++) {
            float s = B1[k];
#pragma unroll
            for (int i = 0; i < FD; i++) s = fmaf(ea[rr*FD + i], __ldg(W1 + i*HH + k), s);
            h[rr] = fmaxf(s, 0.f);
        }
#pragma unroll
        for (int i = 0; i < FD; i++) {
            float s = 0.f;
#pragma unroll
            for (int rr = 0; rr < NR; rr++) s = fmaf(h[rr], ea[rr*FD + i], s);
            a_sh[(k*10 + i)*16 + a] = s;
        }
    }
    // bias rows: sum of e over entities
    for (int idx = tid; idx < 160; idx += 128) {
        int a = idx & 15, i = idx >> 4;
        const float* ea = e_sh + a*161;
        float s = 0.f;
#pragma unroll
        for (int rr = 0; rr < NR; rr++) s += ea[rr*FD + i];
        a_sh[(640 + i)*16 + a] = s;
    }
    __syncthreads();

    // main loop: identical shape to the per-row kernel; lanes = agents
    const int c0 = tid * 2;
    ull acc[8][2];
#pragma unroll
    for (int p = 0; p < 8; p++) { acc[p][0] = 0ull; acc[p][1] = 0ull; }

    for (int k = 0; k < 64; k++) {
        const float* wk = W2 + k*strideK + c0;
#pragma unroll
        for (int i = 0; i < 10; i++) {
            float2 wv = __ldg((const float2*)(wk + i*OD));
            ull w0 = pack2(wv.x, wv.x);
            ull w1d = pack2(wv.y, wv.y);
            const ulonglong2* ar = (const ulonglong2*)(a_sh + (k*10 + i)*16);
#pragma unroll
            for (int q = 0; q < 4; q++) {
                ulonglong2 av = ar[q];
                acc[2*q  ][0] = ffma2(av.x, w0,  acc[2*q  ][0]);
                acc[2*q  ][1] = ffma2(av.x, w1d, acc[2*q  ][1]);
                acc[2*q+1][0] = ffma2(av.y, w0,  acc[2*q+1][0]);
                acc[2*q+1][1] = ffma2(av.y, w1d, acc[2*q+1][1]);
            }
        }
    }
#pragma unroll
    for (int i = 0; i < 10; i++) {
        float2 wv = __ldg((const float2*)(B2 + i*OD + c0));
        ull w0 = pack2(wv.x, wv.x);
        ull w1d = pack2(wv.y, wv.y);
        const ulonglong2* ar = (const ulonglong2*)(a_sh + (640 + i)*16);
#pragma unroll
        for (int q = 0; q < 4; q++) {
            ulonglong2 av = ar[q];
            acc[2*q  ][0] = ffma2(av.x, w0,  acc[2*q  ][0]);
            acc[2*q  ][1] = ffma2(av.x, w1d, acc[2*q  ][1]);
            acc[2*q+1][0] = ffma2(av.y, w0,  acc[2*q+1][0]);
            acc[2*q+1][1] = ffma2(av.y, w1d, acc[2*q+1][1]);
        }
    }

    float* outp = ENEMY ? g_EmbEn : g_EmbAlSum;
#pragma unroll
    for (int p = 0; p < 8; p++) {
        float2 f0 = unpack2(acc[p][0]);   // col c0:   agents 2p, 2p+1
        float2 f1 = unpack2(acc[p][1]);   // col c0+1: agents 2p, 2p+1
        *(ull*)&outp[(ag0 + 2*p    )*OD + c0] = pack2(f0.x, f1.x);
        *(ull*)&outp[(ag0 + 2*p + 1)*OD + c0] = pack2(f0.y, f1.y);
    }
}

// ---------------------------------------------------------------------------
// Ally passing path: per-row GEMM against W2p (= pre-relu layer-1 activations),
// then relu(+pb1), @pw2, mean over heads, max over allies.
__global__ void __launch_bounds__(128) ally_pass_kernel(
    const float* __restrict__ feats,
    const float* __restrict__ W1, const float* __restrict__ B1,
    const float* __restrict__ pb1, const float* __restrict__ pw2,
    const float* __restrict__ pb2)
{
    __shared__ __align__(16) float a_sh[KK*16];   // reused as t_sh in epilogue
    __shared__ __align__(16) float h_sh[HH*16];   // reused as p_sh in epilogue
    __shared__ __align__(16) float e_sh[16*FD];
    const int tid = threadIdx.x;
    const int r0 = blockIdx.x;
    const int rowbase = r0 * NALLY;

    for (int idx = tid; idx < 16*FD; idx += 128) {
        float v = 0.f;
        if (idx < NALLY*FD) v = feats[rowbase*FD + idx];
        e_sh[idx] = v;
    }
    __syncthreads();

#pragma unroll
    for (int p = 0; p < 8; p++) {
        int idx = tid + p*128;
        int rr = idx & 15, k = idx >> 4;
        float s = 0.f;
        if (rr < NALLY) {
            s = B1[k];
#pragma unroll
            for (int i = 0; i < FD; i++) s = fmaf(e_sh[rr*FD + i], __ldg(W1 + i*HH + k), s);
            s = fmaxf(s, 0.f);
        }
        h_sh[idx] = s;
    }
    __syncthreads();

    for (int idx = tid; idx < KK*16; idx += 128) {
        int kk = idx >> 4, rr = idx & 15;
        float v;
        if (kk < 640) {
            int k = kk / 10, i = kk - k*10;
            v = h_sh[k*16 + rr] * e_sh[rr*FD + i];
        } else {
            v = e_sh[rr*FD + (kk - 640)];
        }
        a_sh[idx] = v;
    }
    __syncthreads();

    const int c0 = tid * 2;
    ull acc[8][2];
#pragma unroll
    for (int p = 0; p < 8; p++) { acc[p][0] = 0ull; acc[p][1] = 0ull; }

#pragma unroll 10
    for (int kk = 0; kk < KK; kk++) {
        float2 wv = __ldg((const float2*)(g_W2p + kk*OD + c0));
        ull w0 = pack2(wv.x, wv.x);
        ull w1d = pack2(wv.y, wv.y);
        const ulonglong2* ar = (const ulonglong2*)(a_sh + kk*16);
#pragma unroll
        for (int q = 0; q < 4; q++) {
            ulonglong2 av = ar[q];
            acc[2*q  ][0] = ffma2(av.x, w0,  acc[2*q  ][0]);
            acc[2*q  ][1] = ffma2(av.x, w1d, acc[2*q  ][1]);
            acc[2*q+1][0] = ffma2(av.y, w0,  acc[2*q+1][0]);
            acc[2*q+1][1] = ffma2(av.y, w1d, acc[2*q+1][1]);
        }
    }

    // epilogue: t = relu(z + pb1[j]); t_sh[col*20 + row]
    __syncthreads();
    float* t_sh = a_sh;
    const float bb0 = pb1[c0 & 63];
    const float bb1 = pb1[(c0 + 1) & 63];
#pragma unroll
    for (int p = 0; p < 8; p++) {
        float2 f0 = unpack2(acc[p][0]);
        float2 f1 = unpack2(acc[p][1]);
        *(ull*)(t_sh + c0*20 + 2*p)       = pack2(fmaxf(f0.x + bb0, 0.f), fmaxf(f0.y + bb0, 0.f));
        *(ull*)(t_sh + (c0+1)*20 + 2*p)   = pack2(fmaxf(f1.x + bb1, 0.f), fmaxf(f1.y + bb1, 0.f));
    }
    __syncthreads();

    // layer 2: p[row,hd,c] = sum_m t[row, hd*64+m] * pw2[m*3+c]; 96 threads
    float* p_sh = h_sh;   // 12*16 floats
    if (tid < 96) {
        int hd = tid / 24, rem = tid - hd*24, cc = rem >> 3, rp = rem & 7;
        ull ap = 0ull;
#pragma unroll 8
        for (int m = 0; m < 64; m++) {
            float wv = __ldg(pw2 + m*3 + cc);
            ull wd = pack2(wv, wv);
            ull tv = *(const ull*)(t_sh + (hd*64 + m)*20 + 2*rp);
            ap = ffma2(tv, wd, ap);
        }
        float2 f = unpack2(ap);
        p_sh[(hd*3 + cc)*16 + 2*rp]     = f.x;
        p_sh[(hd*3 + cc)*16 + 2*rp + 1] = f.y;
    }
    __syncthreads();

    if (tid < 3) {
        float mx = -INFINITY;
        float bb = pb2[tid];
        for (int row = 0; row < NALLY; row++) {
            float v = 0.25f * (p_sh[(0*3 + tid)*16 + row] + p_sh[(1*3 + tid)*16 + row] +
                               p_sh[(2*3 + tid)*16 + row] + p_sh[(3*3 + tid)*16 + row]) + bb;
            mx = fmaxf(mx, v);
        }
        g_PassEmb[r0*3 + tid] = mx;
    }
}

// ---------------------------------------------------------------------------
// Final: own-embed + merger softmax + GRU + fc2 + concat outputs
__global__ void __launch_bounds__(64) final_kernel(
    const float* __restrict__ own,
    const float* __restrict__ fc1_w, const float* __restrict__ fc1_b,
    const float* __restrict__ merger_w,
    const float* __restrict__ hstate,
    const float* __restrict__ wih, const float* __restrict__ whh,
    const float* __restrict__ bih, const float* __restrict__ bhh,
    const float* __restrict__ fc2_w1, const float* __restrict__ fc2_b1,
    const float* __restrict__ fc2_w2, const float* __restrict__ fc2_b2,
    float* __restrict__ out_q, float* __restrict__ out_h) {
    __shared__ float own_sh[32];
    __shared__ float x_sh[64];
    __shared__ float h_sh[64];
    __shared__ float hh_sh[64];
    __shared__ float t_sh[64];
    const int r = blockIdx.x;
    const int j = threadIdx.x;   // 64 threads
    if (j < 30) own_sh[j] = own[r*30 + j];
    h_sh[j] = hstate[r*64 + j];
    __syncthreads();

    float eo = fc1_b[j];
#pragma unroll
    for (int i = 0; i < 30; i++) eo = fmaf(own_sh[i], fc1_w[i*64 + j], eo);

    float w0 = merger_w[j], w1v = merger_w[64+j], w2v = merger_w[128+j], w3v = merger_w[192+j];
    float mx = fmaxf(fmaxf(w0, w1v), fmaxf(w2v, w3v));
    float e0 = expf(w0-mx), e1 = expf(w1v-mx), e2 = expf(w2v-mx), e3 = expf(w3v-mx);
    float inv = 1.f / (e0+e1+e2+e3);
    const float* en = g_EmbEn + r*OD;
    const float* al = g_EmbAlSum + r*OD;
    float m = e0*inv*(en[j]      + al[j])
            + e1*inv*(en[64+j]   + al[64+j])
            + e2*inv*(en[128+j]  + al[128+j])
            + e3*inv*(en[192+j]  + al[192+j]);

    float x = fmaxf(eo + m, 0.f);
    x_sh[j] = x;
    __syncthreads();

    float gi[3], gh[3];
#pragma unroll
    for (int t = 0; t < 3; t++) {
        int g = t*64 + j;
        float si = bih[g], sh = bhh[g];
        const float* wi = wih + g*64;
        const float* wh = whh + g*64;
#pragma unroll 8
        for (int k = 0; k < 64; k++) {
            si = fmaf(x_sh[k], __ldg(wi + k), si);
            sh = fmaf(h_sh[k], __ldg(wh + k), sh);
        }
        gi[t] = si; gh[t] = sh;
    }
    float rg = 1.f/(1.f + expf(-(gi[0]+gh[0])));
    float zg = 1.f/(1.f + expf(-(gi[1]+gh[1])));
    float ng = tanhf(gi[2] + rg*gh[2]);
    float hh = (1.f - zg)*ng + zg*h_sh[j];
    hh_sh[j] = hh;
    out_h[r*64 + j] = hh;
    __syncthreads();

    float tt = fc2_b1[j];
#pragma unroll 8
    for (int k = 0; k < 64; k++) tt = fmaf(hh_sh[k], fc2_w1[k*64 + j], tt);
    t_sh[j] = fmaxf(tt, 0.f);
    __syncthreads();

    if (j < 19) {
        float q = fc2_b2[j];
        for (int mm = 0; mm < 64; mm++) q = fmaf(t_sh[mm], fc2_w2[mm*19 + j], q);
        int col = (j < 9) ? j : j + 3;
        out_q[r*22 + col] = q;
    }
    if (j < 3) out_q[r*22 + 9 + j] = g_PassEmb[r*3 + j];
}

extern "C" void kernel_launch(void* const* d_in, const int* in_sizes, int n_in,
                              void* d_out, int out_size) {
    const float* own    = (const float*)d_in[1];
    const float* ally   = (const float*)d_in[2];
    const float* enemy  = (const float*)d_in[3];
    const float* hstate = (const float*)d_in[4];
    const float* fc1_w  = (const float*)d_in[5];
    const float* fc1_b  = (const float*)d_in[6];
    const float* he_w1  = (const float*)d_in[7];
    const float* he_b1  = (const float*)d_in[8];
    const float* he_w2  = (const float*)d_in[9];
    const float* he_b2  = (const float*)d_in[10];
    const float* ha_w1  = (const float*)d_in[11];
    const float* ha_b1  = (const float*)d_in[12];
    const float* ha_w2  = (const float*)d_in[13];
    const float* ha_b2  = (const float*)d_in[14];
    const float* merger = (const float*)d_in[15];
    const float* wih    = (const float*)d_in[16];
    const float* whh    = (const float*)d_in[17];
    const float* bih    = (const float*)d_in[18];
    const float* bhh    = (const float*)d_in[19];
    const float* fc2_w1 = (const float*)d_in[20];
    const float* fc2_b1 = (const float*)d_in[21];
    const float* fc2_w2 = (const float*)d_in[22];
    const float* fc2_b2 = (const float*)d_in[23];
    const float* pw1    = (const float*)d_in[24];
    const float* pb1    = (const float*)d_in[25];
    const float* pw2    = (const float*)d_in[26];
    const float* pb2    = (const float*)d_in[27];

    float* out   = (float*)d_out;
    float* out_q = out;              // [2048, 22]
    float* out_h = out + RR*22;      // [2048, 64]

    w2p_kernel<<<KK, 256>>>(ha_w2, ha_b2, pw1);
    summed_kernel<NEN,   true ><<<RR/16, 128>>>(enemy, he_w1, he_b1, he_w2, he_b2, 2820);
    summed_kernel<NALLY, false><<<RR/16, 128>>>(ally,  ha_w1, ha_b1, ha_w2, ha_b2, 2560);
    ally_pass_kernel<<<RR, 128>>>(ally, ha_w1, ha_b1, pb1, pw2, pb2);
    final_kernel<<<RR, 64>>>(own, fc1_w, fc1_b, merger, hstate,
                             wih, whh, bih, bhh,
                             fc2_w1, fc2_b1, fc2_w2, fc2_b2,
                             out_q, out_h);
}